// round 13
// baseline (speedup 1.0000x reference)
#include <cuda_runtime.h>
#include <cstdint>

// ====== NuggetScorer — R13: TF32 rank + warp-per-candidate fp32 rescore =====
#define BB 8
#define SS 4096
#define DD 2048
#define HH 128
#define MN 410
#define MM (BB*SS)

#define ENC_SZ ((size_t)BB*MN*DD)
#define BMN (BB*MN)

#define NCAND 512
#define RCPB 16                // candidates per rescore block (1 per warp)
#define RKC 512                // rescore k-chunk

// GEMM config (single-level TF32)
#define KC 16
#define NCH (DD/KC)            // 128
#define LVLF 2048
#define AFRAG LVLF             // 2048
#define BFRAG LVLF             // 2048
#define STAGEF (AFRAG+BFRAG)   // 4096
#define REDF (128*17)
#define SMEM_FLOATS (2*STAGEF + REDF + 256)
#define SMEM_BYTES (SMEM_FLOATS*4)

__device__ float r13_bfrag[NCH*BFRAG];
__device__ float r13_scores[MM];
__device__ int   r13_cand[BB*NCAND];
__device__ float r13_cscore[BB*NCAND];
__device__ int   r13_nn[BB];
__device__ int   r13_idx[BB*MN];

typedef unsigned long long ull;

__device__ __forceinline__ float r13_tf32(float x) {
    uint32_t r; asm("cvt.rna.tf32.f32 %0,%1;" : "=r"(r) : "f"(x));
    return __uint_as_float(r);
}
__device__ __forceinline__ void r13_mma(float* d, const uint32_t* a, const uint32_t* b) {
    asm volatile("mma.sync.aligned.m16n8k8.row.col.f32.tf32.tf32.f32 "
        "{%0,%1,%2,%3},{%4,%5,%6,%7},{%8,%9},{%0,%1,%2,%3};"
        : "+f"(d[0]), "+f"(d[1]), "+f"(d[2]), "+f"(d[3])
        : "r"(a[0]), "r"(a[1]), "r"(a[2]), "r"(a[3]), "r"(b[0]), "r"(b[1]));
}
__device__ __forceinline__ ull r13_pack2(float x, float y) {
    ull r; asm("mov.b64 %0,{%1,%2};" : "=l"(r) : "f"(x), "f"(y)); return r;
}
__device__ __forceinline__ void r13_unpack2(ull v, float& x, float& y) {
    asm("mov.b64 {%0,%1},%2;" : "=f"(x), "=f"(y) : "l"(v));
}
__device__ __forceinline__ void r13_ffma2(ull& d, ull a, ull b) {
    asm("fma.rn.f32x2 %0,%1,%2,%0;" : "+l"(d) : "l"(a), "l"(b));
}

// ---------------------------------------------------------------------------
// Kernel 0: W1 -> single-level tf32 fragments (fragment-major per chunk)
// ---------------------------------------------------------------------------
__global__ __launch_bounds__(256) void r13_bprep(const float* __restrict__ w1)
{
    int idx = blockIdx.x * 256 + threadIdx.x;    // 0 .. 262143
    int k = idx >> 7, n = idx & 127;
    float h0 = r13_tf32(w1[idx]);                 // w1[k][n]
    int ch = k >> 4, kk = k & 15;
    int ks = kk >> 3, c2 = kk & 7;
    int nb = n >> 3;
    int lane = ((n & 7) << 2) | (c2 & 3);
    int slot = c2 >> 2;
    r13_bfrag[ch * BFRAG + ((nb * 2 + ks) << 6) + (lane << 1) + slot] = h0;
}

// ---------------------------------------------------------------------------
// Kernel 1: approx score GEMM, single-term TF32 (mma.sync).
// ---------------------------------------------------------------------------
extern __shared__ float r13_dsm[];

__global__ __launch_bounds__(256) void r13_score(
    const float* __restrict__ A, const float* __restrict__ bias1,
    const float* __restrict__ w2v, const float* __restrict__ bias2,
    float* __restrict__ scores_out)
{
    const int tid  = threadIdx.x;
    const int lane = tid & 31;
    const int wid  = tid >> 5;
    const int wy   = wid >> 2;
    const int wx   = wid & 3;
    const int row0 = blockIdx.x * 128;

    float* red = r13_dsm + 2 * STAGEF;
    float* b1s = red + REDF;
    float* w2s = b1s + HH;
    if (tid < HH) { b1s[tid] = bias1[tid]; w2s[tid] = w2v[tid]; }

    const int rr0 = tid >> 2;
    const int q   = tid & 3;
    int aoff[8];
#pragma unroll
    for (int e = 0; e < 8; e++) {
        int rr = (e < 4) ? rr0 : rr0 + 64;
        int col = q * 4 + (e & 3);
        int ks = col >> 3, cc = col & 7;
        int mt = rr >> 4, r = rr & 15;
        int lw = ((r & 7) << 2) | (cc & 3);
        int slot = ((cc >> 2) << 1) | (r >> 3);
        aoff[e] = ((mt * 2 + ks) << 7) + (lw << 2) + slot;
    }

    float acc[4][4][4];
#pragma unroll
    for (int i = 0; i < 4; i++)
#pragma unroll
        for (int j = 0; j < 4; j++)
#pragma unroll
            for (int v = 0; v < 4; v++) acc[i][j][v] = 0.f;

    float4 sa0, sa1, sb[2];

    sa0 = *(const float4*)(A + (size_t)(row0 + rr0) * DD + q * 4);
    sa1 = *(const float4*)(A + (size_t)(row0 + rr0 + 64) * DD + q * 4);
#pragma unroll
    for (int i = 0; i < 2; i++)
        sb[i] = __ldg((const float4*)(r13_bfrag + (size_t)(tid + i * 256) * 4));

    {
        float* st = r13_dsm;
        float av[8] = {sa0.x, sa0.y, sa0.z, sa0.w, sa1.x, sa1.y, sa1.z, sa1.w};
#pragma unroll
        for (int e = 0; e < 8; e++) st[aoff[e]] = r13_tf32(av[e]);
#pragma unroll
        for (int i = 0; i < 2; i++)
            *(float4*)(st + AFRAG + (tid + i * 256) * 4) = sb[i];
    }
    __syncthreads();

    for (int c = 0; c < NCH; ++c) {
        const int cur = c & 1;
        const float* st = r13_dsm + cur * STAGEF;

        if (c + 1 < NCH) {
            int k0 = (c + 1) * KC;
            sa0 = *(const float4*)(A + (size_t)(row0 + rr0) * DD + k0 + q * 4);
            sa1 = *(const float4*)(A + (size_t)(row0 + rr0 + 64) * DD + k0 + q * 4);
#pragma unroll
            for (int i = 0; i < 2; i++)
                sb[i] = __ldg((const float4*)(r13_bfrag + (size_t)(c + 1) * BFRAG + (size_t)(tid + i * 256) * 4));
        }

#pragma unroll
        for (int ks = 0; ks < 2; ks++) {
            const float* Ab = st;
            const float* Bb = st + AFRAG;
            uint32_t a0[4][4], b0[4][2];
#pragma unroll
            for (int mt = 0; mt < 4; mt++) {
                float4 v = *(const float4*)(Ab + (((wy * 4 + mt) * 2 + ks) << 7) + (lane << 2));
                a0[mt][0] = __float_as_uint(v.x); a0[mt][1] = __float_as_uint(v.y);
                a0[mt][2] = __float_as_uint(v.z); a0[mt][3] = __float_as_uint(v.w);
            }
#pragma unroll
            for (int nt = 0; nt < 4; nt++) {
                float2 v = *(const float2*)(Bb + (((wx * 4 + nt) * 2 + ks) << 6) + (lane << 1));
                b0[nt][0] = __float_as_uint(v.x); b0[nt][1] = __float_as_uint(v.y);
            }
#pragma unroll
            for (int mt = 0; mt < 4; mt++)
#pragma unroll
                for (int nt = 0; nt < 4; nt++)
                    r13_mma(acc[mt][nt], a0[mt], b0[nt]);
        }

        if (c + 1 < NCH) {
            float* st2 = r13_dsm + (cur ^ 1) * STAGEF;
            float av[8] = {sa0.x, sa0.y, sa0.z, sa0.w, sa1.x, sa1.y, sa1.z, sa1.w};
#pragma unroll
            for (int e = 0; e < 8; e++) st2[aoff[e]] = r13_tf32(av[e]);
#pragma unroll
            for (int i = 0; i < 2; i++)
                *(float4*)(st2 + AFRAG + (tid + i * 256) * 4) = sb[i];
        }
        __syncthreads();
    }

    const int mrow = lane >> 2;
    const int kcol = lane & 3;
#pragma unroll
    for (int mt = 0; mt < 4; mt++)
#pragma unroll
        for (int h = 0; h < 2; h++) {
            int row = (wy * 4 + mt) * 16 + mrow + 8 * h;
            float part = 0.f;
#pragma unroll
            for (int nt = 0; nt < 4; nt++) {
                int col = (wx * 4 + nt) * 8 + 2 * kcol;
                float x0 = acc[mt][nt][2 * h]     + b1s[col];
                float x1 = acc[mt][nt][2 * h + 1] + b1s[col + 1];
                float g0 = 0.5f * x0 * (1.0f + erff(x0 * 0.7071067811865476f));
                float g1 = 0.5f * x1 * (1.0f + erff(x1 * 0.7071067811865476f));
                part = fmaf(g0, w2s[col], part);
                part = fmaf(g1, w2s[col + 1], part);
            }
            red[row * 17 + wx * 4 + kcol] = part;
        }
    __syncthreads();

    if (tid < 128) {
        float s = bias2[0];
#pragma unroll
        for (int j = 0; j < 16; j++) s += red[tid * 17 + j];
        scores_out[row0 + tid] = s;
        r13_scores[row0 + tid] = s;
    }
}

// ---------------------------------------------------------------------------
// Kernel 2: per-batch bitonic sort of approx scores -> top-NCAND candidates.
// ---------------------------------------------------------------------------
__global__ __launch_bounds__(1024) void r13_cand_topk(const int* __restrict__ mask)
{
    __shared__ ull key[SS];
    __shared__ int sh_cnt;
    const int b = blockIdx.x;
    const int tid = threadIdx.x;
    if (tid == 0) sh_cnt = 0;
    __syncthreads();

    const float* srow = r13_scores + (size_t)b * SS;
    const int*   mrow = mask + (size_t)b * SS;

    int cnt = 0;
    for (int i = tid; i < SS; i += 1024) {
        float f = srow[i];
        unsigned u = __float_as_uint(f);
        u = (u & 0x80000000u) ? ~u : (u | 0x80000000u);
        key[i] = ((ull)u << 12) | (ull)(SS - 1 - i);
        cnt += mrow[i];
    }
#pragma unroll
    for (int o = 16; o > 0; o >>= 1) cnt += __shfl_down_sync(0xffffffffu, cnt, o);
    if ((tid & 31) == 0) atomicAdd(&sh_cnt, cnt);
    __syncthreads();

    for (int k = 2; k <= SS; k <<= 1) {
        for (int j = k >> 1; j > 0; j >>= 1) {
            for (int i = tid; i < SS; i += 1024) {
                int l = i ^ j;
                if (l > i) {
                    ull a = key[i], cc = key[l];
                    bool desc = ((i & k) == 0);
                    if (desc ? (a < cc) : (a > cc)) { key[i] = cc; key[l] = a; }
                }
            }
            __syncthreads();
        }
    }

    if (tid == 0) {
        int ntok = sh_cnt;
        int nn = (int)ceilf((float)ntok * 0.1f);
        nn = max(nn, 1);
        nn = min(nn, ntok);
        r13_nn[b] = nn;
    }
    if (tid < NCAND)
        r13_cand[b * NCAND + tid] = (SS - 1) - (int)(key[tid] & 0xFFFull);
}

// ---------------------------------------------------------------------------
// Kernel 3: exact fp32 rescore — one WARP per candidate.
// 512 threads = 16 warps; lane owns 4 hidden cols; per k: broadcast LDS.32 of
// a (staged lhs row), coalesced LDG.128 of w1 row, 2 FFMA2.
// Serial ascending-k chain per (cand, col) — the accumulation class that
// matched the reference in R10/R12.
// ---------------------------------------------------------------------------
__global__ __launch_bounds__(512) void r13_rescore(
    const float* __restrict__ lhs, const float* __restrict__ w1,
    const float* __restrict__ bias1, const float* __restrict__ w2v,
    const float* __restrict__ bias2)
{
    __shared__ float sA[RCPB][RKC];      // 32 KB
    __shared__ int rows[RCPB];

    const int tid  = threadIdx.x;
    const int wid  = tid >> 5;           // warp = candidate
    const int lane = tid & 31;
    const int cand0 = blockIdx.x * RCPB;
    const int b = cand0 / NCAND;

    if (tid < RCPB) rows[tid] = r13_cand[cand0 + tid];
    __syncthreads();

    ull h2[2] = {0ull, 0ull};            // cols 4*lane .. 4*lane+3
    const float* wcol = w1 + lane * 4;

    for (int ch = 0; ch < DD / RKC; ch++) {     // 4 chunks
        // stage 16 candidate rows x RKC floats (coalesced)
#pragma unroll
        for (int s = 0; s < 4; s++) {
            int lin = tid + s * 512;            // 0..2047
            int r = lin >> 7, c4 = lin & 127;
            *(float4*)(&sA[r][c4 * 4]) =
                *(const float4*)(lhs + ((size_t)b * SS + rows[r]) * DD + ch * RKC + c4 * 4);
        }
        __syncthreads();

        const float* arow = sA[wid];
#pragma unroll 8
        for (int k = 0; k < RKC; k++) {
            float a = arow[k];                               // LDS broadcast
            float4 w4 = __ldg((const float4*)(wcol + (size_t)(ch * RKC + k) * HH));
            ull ap = r13_pack2(a, a);
            r13_ffma2(h2[0], r13_pack2(w4.x, w4.y), ap);
            r13_ffma2(h2[1], r13_pack2(w4.z, w4.w), ap);
        }
        __syncthreads();
    }

    // epilogue: gelu + dot(w2) over this lane's 4 cols, then warp reduce
    float h[4];
    r13_unpack2(h2[0], h[0], h[1]);
    r13_unpack2(h2[1], h[2], h[3]);
    float p = 0.f;
#pragma unroll
    for (int t = 0; t < 4; t++) {
        int j = lane * 4 + t;
        float x = h[t] + __ldg(bias1 + j);
        float g = 0.5f * x * (1.0f + erff(x * 0.7071067811865476f));
        p = fmaf(g, __ldg(w2v + j), p);
    }
#pragma unroll
    for (int o = 16; o > 0; o >>= 1) p += __shfl_down_sync(0xffffffffu, p, o);
    if (lane == 0) r13_cscore[cand0 + wid] = p + bias2[0];
}

// ---------------------------------------------------------------------------
// Kernel 4: final per-batch sort of NCAND rescored candidates -> outputs.
// ---------------------------------------------------------------------------
__global__ __launch_bounds__(NCAND) void r13_final(
    float* __restrict__ o_mask, float* __restrict__ o_ns, float* __restrict__ o_idx)
{
    __shared__ ull key[NCAND];
    const int b = blockIdx.x;
    const int tid = threadIdx.x;

    {
        float f = r13_cscore[b * NCAND + tid];
        int idx = r13_cand[b * NCAND + tid];
        unsigned u = __float_as_uint(f);
        u = (u & 0x80000000u) ? ~u : (u | 0x80000000u);
        key[tid] = ((ull)u << 12) | (ull)(SS - 1 - idx);
    }
    __syncthreads();

    for (int k = 2; k <= NCAND; k <<= 1) {
        for (int j = k >> 1; j > 0; j >>= 1) {
            int l = tid ^ j;
            if (l > tid) {
                ull a = key[tid], cc = key[l];
                bool desc = ((tid & k) == 0);
                if (desc ? (a < cc) : (a > cc)) { key[tid] = cc; key[l] = a; }
            }
            __syncthreads();
        }
    }

    if (tid < MN) {
        ull kk = key[tid];
        int idx = (SS - 1) - (int)(kk & 0xFFFull);
        unsigned u = (unsigned)(kk >> 12);
        u = (u & 0x80000000u) ? (u & 0x7FFFFFFFu) : ~u;
        int nn = r13_nn[b];
        o_idx[b * MN + tid]  = (float)idx;
        o_ns[b * MN + tid]   = __uint_as_float(u);
        o_mask[b * MN + tid] = (tid < nn) ? 1.0f : 0.0f;
        r13_idx[b * MN + tid] = idx;
    }
}

// ---------------------------------------------------------------------------
// Kernel 5: gather enc rows.
// ---------------------------------------------------------------------------
__global__ __launch_bounds__(512) void r13_gather(
    const float* __restrict__ hidden, float* __restrict__ enc)
{
    int t = blockIdx.x;
    int b = t / MN;
    int s = r13_idx[t];
    const float4* src = (const float4*)(hidden + ((size_t)b * SS + s) * DD);
    float4* dst = (float4*)(enc + (size_t)t * DD);
    dst[threadIdx.x] = src[threadIdx.x];
}

// ---------------------------------------------------------------------------
extern "C" void kernel_launch(void* const* d_in, const int* in_sizes, int n_in,
                              void* d_out, int out_size)
{
    const float* lhs  = (const float*)d_in[0];
    const float* hid  = (const float*)d_in[1];
    const int*   mask = (const int*)  d_in[2];
    const float* w1   = (const float*)d_in[3];
    const float* b1   = (const float*)d_in[4];
    const float* w2   = (const float*)d_in[5];
    const float* b2   = (const float*)d_in[6];

    float* out = (float*)d_out;
    float* o_enc    = out;
    float* o_mask   = out + ENC_SZ;
    float* o_ns     = o_mask + BMN;
    float* o_idx    = o_ns + BMN;
    float* o_scores = o_idx + BMN;

    cudaFuncSetAttribute(r13_score,
                         cudaFuncAttributeMaxDynamicSharedMemorySize, SMEM_BYTES);

    r13_bprep<<<(HH * DD) / 256, 256>>>(w1);
    r13_score<<<MM / 128, 256, SMEM_BYTES>>>(lhs, b1, w2, b2, o_scores);
    r13_cand_topk<<<BB, 1024>>>(mask);
    r13_rescore<<<BB * NCAND / RCPB, 512>>>(lhs, w1, b1, w2, b2);
    r13_final<<<BB, NCAND>>>(o_mask, o_ns, o_idx);
    r13_gather<<<BB * MN, 512>>>(hid, o_enc);
}

// round 16
// speedup vs baseline: 1.0663x; 1.0663x over previous
#include <cuda_runtime.h>
#include <cstdint>

// ====== NuggetScorer — R16 (= R15 resubmit): TF32 rank + 4cand/warp rescore =
#define BB 8
#define SS 4096
#define DD 2048
#define HH 128
#define MN 410
#define MM (BB*SS)

#define ENC_SZ ((size_t)BB*MN*DD)
#define BMN (BB*MN)

#define NCAND 512
#define RCPB 64                // candidates per rescore block
#define RCPW 4                 // candidates per warp
#define RKC 128                // rescore k-chunk (stage 64 x 128 floats = 32KB)

// GEMM config (single-level TF32)
#define KC 16
#define NCH (DD/KC)            // 128
#define LVLF 2048
#define AFRAG LVLF             // 2048
#define BFRAG LVLF             // 2048
#define STAGEF (AFRAG+BFRAG)   // 4096
#define REDF (128*17)
#define SMEM_FLOATS (2*STAGEF + REDF + 256)
#define SMEM_BYTES (SMEM_FLOATS*4)

__device__ float r16_bfrag[NCH*BFRAG];
__device__ float r16_scores[MM];
__device__ int   r16_cand[BB*NCAND];
__device__ float r16_cscore[BB*NCAND];
__device__ int   r16_nn[BB];
__device__ int   r16_idx[BB*MN];

typedef unsigned long long ull;

__device__ __forceinline__ float r16_tf32(float x) {
    uint32_t r; asm("cvt.rna.tf32.f32 %0,%1;" : "=r"(r) : "f"(x));
    return __uint_as_float(r);
}
__device__ __forceinline__ void r16_mma(float* d, const uint32_t* a, const uint32_t* b) {
    asm volatile("mma.sync.aligned.m16n8k8.row.col.f32.tf32.tf32.f32 "
        "{%0,%1,%2,%3},{%4,%5,%6,%7},{%8,%9},{%0,%1,%2,%3};"
        : "+f"(d[0]), "+f"(d[1]), "+f"(d[2]), "+f"(d[3])
        : "r"(a[0]), "r"(a[1]), "r"(a[2]), "r"(a[3]), "r"(b[0]), "r"(b[1]));
}
__device__ __forceinline__ ull r16_pack2(float x, float y) {
    ull r; asm("mov.b64 %0,{%1,%2};" : "=l"(r) : "f"(x), "f"(y)); return r;
}
__device__ __forceinline__ void r16_unpack2(ull v, float& x, float& y) {
    asm("mov.b64 {%0,%1},%2;" : "=f"(x), "=f"(y) : "l"(v));
}
__device__ __forceinline__ void r16_ffma2(ull& d, ull a, ull b) {
    asm("fma.rn.f32x2 %0,%1,%2,%0;" : "+l"(d) : "l"(a), "l"(b));
}

// ---------------------------------------------------------------------------
// Kernel 0: W1 -> single-level tf32 fragments (fragment-major per chunk)
// ---------------------------------------------------------------------------
__global__ __launch_bounds__(256) void r16_bprep(const float* __restrict__ w1)
{
    int idx = blockIdx.x * 256 + threadIdx.x;    // 0 .. 262143
    int k = idx >> 7, n = idx & 127;
    float h0 = r16_tf32(w1[idx]);                 // w1[k][n]
    int ch = k >> 4, kk = k & 15;
    int ks = kk >> 3, c2 = kk & 7;
    int nb = n >> 3;
    int lane = ((n & 7) << 2) | (c2 & 3);
    int slot = c2 >> 2;
    r16_bfrag[ch * BFRAG + ((nb * 2 + ks) << 6) + (lane << 1) + slot] = h0;
}

// ---------------------------------------------------------------------------
// Kernel 1: approx score GEMM, single-term TF32 (mma.sync).
// ---------------------------------------------------------------------------
extern __shared__ float r16_dsm[];

__global__ __launch_bounds__(256) void r16_score(
    const float* __restrict__ A, const float* __restrict__ bias1,
    const float* __restrict__ w2v, const float* __restrict__ bias2,
    float* __restrict__ scores_out)
{
    const int tid  = threadIdx.x;
    const int lane = tid & 31;
    const int wid  = tid >> 5;
    const int wy   = wid >> 2;
    const int wx   = wid & 3;
    const int row0 = blockIdx.x * 128;

    float* red = r16_dsm + 2 * STAGEF;
    float* b1s = red + REDF;
    float* w2s = b1s + HH;
    if (tid < HH) { b1s[tid] = bias1[tid]; w2s[tid] = w2v[tid]; }

    const int rr0 = tid >> 2;
    const int q   = tid & 3;
    int aoff[8];
#pragma unroll
    for (int e = 0; e < 8; e++) {
        int rr = (e < 4) ? rr0 : rr0 + 64;
        int col = q * 4 + (e & 3);
        int ks = col >> 3, cc = col & 7;
        int mt = rr >> 4, r = rr & 15;
        int lw = ((r & 7) << 2) | (cc & 3);
        int slot = ((cc >> 2) << 1) | (r >> 3);
        aoff[e] = ((mt * 2 + ks) << 7) + (lw << 2) + slot;
    }

    float acc[4][4][4];
#pragma unroll
    for (int i = 0; i < 4; i++)
#pragma unroll
        for (int j = 0; j < 4; j++)
#pragma unroll
            for (int v = 0; v < 4; v++) acc[i][j][v] = 0.f;

    float4 sa0, sa1, sb[2];

    sa0 = *(const float4*)(A + (size_t)(row0 + rr0) * DD + q * 4);
    sa1 = *(const float4*)(A + (size_t)(row0 + rr0 + 64) * DD + q * 4);
#pragma unroll
    for (int i = 0; i < 2; i++)
        sb[i] = __ldg((const float4*)(r16_bfrag + (size_t)(tid + i * 256) * 4));

    {
        float* st = r16_dsm;
        float av[8] = {sa0.x, sa0.y, sa0.z, sa0.w, sa1.x, sa1.y, sa1.z, sa1.w};
#pragma unroll
        for (int e = 0; e < 8; e++) st[aoff[e]] = r16_tf32(av[e]);
#pragma unroll
        for (int i = 0; i < 2; i++)
            *(float4*)(st + AFRAG + (tid + i * 256) * 4) = sb[i];
    }
    __syncthreads();

    for (int c = 0; c < NCH; ++c) {
        const int cur = c & 1;
        const float* st = r16_dsm + cur * STAGEF;

        if (c + 1 < NCH) {
            int k0 = (c + 1) * KC;
            sa0 = *(const float4*)(A + (size_t)(row0 + rr0) * DD + k0 + q * 4);
            sa1 = *(const float4*)(A + (size_t)(row0 + rr0 + 64) * DD + k0 + q * 4);
#pragma unroll
            for (int i = 0; i < 2; i++)
                sb[i] = __ldg((const float4*)(r16_bfrag + (size_t)(c + 1) * BFRAG + (size_t)(tid + i * 256) * 4));
        }

#pragma unroll
        for (int ks = 0; ks < 2; ks++) {
            const float* Ab = st;
            const float* Bb = st + AFRAG;
            uint32_t a0[4][4], b0[4][2];
#pragma unroll
            for (int mt = 0; mt < 4; mt++) {
                float4 v = *(const float4*)(Ab + (((wy * 4 + mt) * 2 + ks) << 7) + (lane << 2));
                a0[mt][0] = __float_as_uint(v.x); a0[mt][1] = __float_as_uint(v.y);
                a0[mt][2] = __float_as_uint(v.z); a0[mt][3] = __float_as_uint(v.w);
            }
#pragma unroll
            for (int nt = 0; nt < 4; nt++) {
                float2 v = *(const float2*)(Bb + (((wx * 4 + nt) * 2 + ks) << 6) + (lane << 1));
                b0[nt][0] = __float_as_uint(v.x); b0[nt][1] = __float_as_uint(v.y);
            }
#pragma unroll
            for (int mt = 0; mt < 4; mt++)
#pragma unroll
                for (int nt = 0; nt < 4; nt++)
                    r16_mma(acc[mt][nt], a0[mt], b0[nt]);
        }

        if (c + 1 < NCH) {
            float* st2 = r16_dsm + (cur ^ 1) * STAGEF;
            float av[8] = {sa0.x, sa0.y, sa0.z, sa0.w, sa1.x, sa1.y, sa1.z, sa1.w};
#pragma unroll
            for (int e = 0; e < 8; e++) st2[aoff[e]] = r16_tf32(av[e]);
#pragma unroll
            for (int i = 0; i < 2; i++)
                *(float4*)(st2 + AFRAG + (tid + i * 256) * 4) = sb[i];
        }
        __syncthreads();
    }

    const int mrow = lane >> 2;
    const int kcol = lane & 3;
#pragma unroll
    for (int mt = 0; mt < 4; mt++)
#pragma unroll
        for (int h = 0; h < 2; h++) {
            int row = (wy * 4 + mt) * 16 + mrow + 8 * h;
            float part = 0.f;
#pragma unroll
            for (int nt = 0; nt < 4; nt++) {
                int col = (wx * 4 + nt) * 8 + 2 * kcol;
                float x0 = acc[mt][nt][2 * h]     + b1s[col];
                float x1 = acc[mt][nt][2 * h + 1] + b1s[col + 1];
                float g0 = 0.5f * x0 * (1.0f + erff(x0 * 0.7071067811865476f));
                float g1 = 0.5f * x1 * (1.0f + erff(x1 * 0.7071067811865476f));
                part = fmaf(g0, w2s[col], part);
                part = fmaf(g1, w2s[col + 1], part);
            }
            red[row * 17 + wx * 4 + kcol] = part;
        }
    __syncthreads();

    if (tid < 128) {
        float s = bias2[0];
#pragma unroll
        for (int j = 0; j < 16; j++) s += red[tid * 17 + j];
        scores_out[row0 + tid] = s;
        r16_scores[row0 + tid] = s;
    }
}

// ---------------------------------------------------------------------------
// Kernel 2: per-batch bitonic sort of approx scores -> top-NCAND candidates.
// ---------------------------------------------------------------------------
__global__ __launch_bounds__(1024) void r16_cand_topk(const int* __restrict__ mask)
{
    __shared__ ull key[SS];
    __shared__ int sh_cnt;
    const int b = blockIdx.x;
    const int tid = threadIdx.x;
    if (tid == 0) sh_cnt = 0;
    __syncthreads();

    const float* srow = r16_scores + (size_t)b * SS;
    const int*   mrow = mask + (size_t)b * SS;

    int cnt = 0;
    for (int i = tid; i < SS; i += 1024) {
        float f = srow[i];
        unsigned u = __float_as_uint(f);
        u = (u & 0x80000000u) ? ~u : (u | 0x80000000u);
        key[i] = ((ull)u << 12) | (ull)(SS - 1 - i);
        cnt += mrow[i];
    }
#pragma unroll
    for (int o = 16; o > 0; o >>= 1) cnt += __shfl_down_sync(0xffffffffu, cnt, o);
    if ((tid & 31) == 0) atomicAdd(&sh_cnt, cnt);
    __syncthreads();

    for (int k = 2; k <= SS; k <<= 1) {
        for (int j = k >> 1; j > 0; j >>= 1) {
            for (int i = tid; i < SS; i += 1024) {
                int l = i ^ j;
                if (l > i) {
                    ull a = key[i], cc = key[l];
                    bool desc = ((i & k) == 0);
                    if (desc ? (a < cc) : (a > cc)) { key[i] = cc; key[l] = a; }
                }
            }
            __syncthreads();
        }
    }

    if (tid == 0) {
        int ntok = sh_cnt;
        int nn = (int)ceilf((float)ntok * 0.1f);
        nn = max(nn, 1);
        nn = min(nn, ntok);
        r16_nn[b] = nn;
    }
    if (tid < NCAND)
        r16_cand[b * NCAND + tid] = (SS - 1) - (int)(key[tid] & 0xFFFull);
}

// ---------------------------------------------------------------------------
// Kernel 3: exact fp32 rescore — 4 candidates per warp (w-load amortized 4x).
// 512 threads = 16 warps; block covers 64 candidates. Lane owns 4 hidden cols.
// Per k: 1 LDG.128 (w row, warp-shared) + 4 broadcast LDS.32 (a) + 8 FFMA2.
// Serial ascending-k chain per (cand, col) — same class as R10/R12 (passed).
// ---------------------------------------------------------------------------
__global__ __launch_bounds__(512) void r16_rescore(
    const float* __restrict__ lhs, const float* __restrict__ w1,
    const float* __restrict__ bias1, const float* __restrict__ w2v,
    const float* __restrict__ bias2)
{
    __shared__ float sA[RCPB][RKC];      // 64 x 128 x 4B = 32 KB
    __shared__ int rows[RCPB];

    const int tid  = threadIdx.x;
    const int wid  = tid >> 5;           // warp -> candidates wid*4 .. +3
    const int lane = tid & 31;
    const int cand0 = blockIdx.x * RCPB;
    const int b = cand0 / NCAND;

    if (tid < RCPB) rows[tid] = r16_cand[cand0 + tid];
    __syncthreads();

    ull h2[RCPW][2];
#pragma unroll
    for (int c = 0; c < RCPW; c++) { h2[c][0] = 0ull; h2[c][1] = 0ull; }

    const float* wcol = w1 + lane * 4;

    for (int ch = 0; ch < DD / RKC; ch++) {     // 16 chunks
        // stage 64 candidate rows x RKC floats (coalesced, 4 float4/thread)
#pragma unroll
        for (int s = 0; s < 4; s++) {
            int lin = tid + s * 512;            // 0..2047
            int r = lin >> 5, c4 = lin & 31;
            *(float4*)(&sA[r][c4 * 4]) =
                *(const float4*)(lhs + ((size_t)b * SS + rows[r]) * DD + ch * RKC + c4 * 4);
        }
        __syncthreads();

        const float* a0 = sA[wid * RCPW + 0];
        const float* a1 = sA[wid * RCPW + 1];
        const float* a2 = sA[wid * RCPW + 2];
        const float* a3 = sA[wid * RCPW + 3];

#pragma unroll 4
        for (int k = 0; k < RKC; k++) {
            float4 w4 = __ldg((const float4*)(wcol + (size_t)(ch * RKC + k) * HH));
            ull wlo = r16_pack2(w4.x, w4.y);
            ull whi = r16_pack2(w4.z, w4.w);
            ull ap0 = r16_pack2(a0[k], a0[k]);
            ull ap1 = r16_pack2(a1[k], a1[k]);
            ull ap2 = r16_pack2(a2[k], a2[k]);
            ull ap3 = r16_pack2(a3[k], a3[k]);
            r16_ffma2(h2[0][0], wlo, ap0); r16_ffma2(h2[0][1], whi, ap0);
            r16_ffma2(h2[1][0], wlo, ap1); r16_ffma2(h2[1][1], whi, ap1);
            r16_ffma2(h2[2][0], wlo, ap2); r16_ffma2(h2[2][1], whi, ap2);
            r16_ffma2(h2[3][0], wlo, ap3); r16_ffma2(h2[3][1], whi, ap3);
        }
        __syncthreads();
    }

    // epilogue: per candidate: gelu + dot(w2) over lane's 4 cols, warp reduce
    float b1v[4], w2vv[4];
#pragma unroll
    for (int t = 0; t < 4; t++) {
        b1v[t]  = __ldg(bias1 + lane * 4 + t);
        w2vv[t] = __ldg(w2v + lane * 4 + t);
    }
    float bb2 = bias2[0];
#pragma unroll
    for (int c = 0; c < RCPW; c++) {
        float h[4];
        r16_unpack2(h2[c][0], h[0], h[1]);
        r16_unpack2(h2[c][1], h[2], h[3]);
        float p = 0.f;
#pragma unroll
        for (int t = 0; t < 4; t++) {
            float x = h[t] + b1v[t];
            float g = 0.5f * x * (1.0f + erff(x * 0.7071067811865476f));
            p = fmaf(g, w2vv[t], p);
        }
#pragma unroll
        for (int o = 16; o > 0; o >>= 1) p += __shfl_down_sync(0xffffffffu, p, o);
        if (lane == 0) r16_cscore[cand0 + wid * RCPW + c] = p + bb2;
    }
}

// ---------------------------------------------------------------------------
// Kernel 4: final per-batch sort of NCAND rescored candidates -> outputs.
// ---------------------------------------------------------------------------
__global__ __launch_bounds__(NCAND) void r16_final(
    float* __restrict__ o_mask, float* __restrict__ o_ns, float* __restrict__ o_idx)
{
    __shared__ ull key[NCAND];
    const int b = blockIdx.x;
    const int tid = threadIdx.x;

    {
        float f = r16_cscore[b * NCAND + tid];
        int idx = r16_cand[b * NCAND + tid];
        unsigned u = __float_as_uint(f);
        u = (u & 0x80000000u) ? ~u : (u | 0x80000000u);
        key[tid] = ((ull)u << 12) | (ull)(SS - 1 - idx);
    }
    __syncthreads();

    for (int k = 2; k <= NCAND; k <<= 1) {
        for (int j = k >> 1; j > 0; j >>= 1) {
            int l = tid ^ j;
            if (l > tid) {
                ull a = key[tid], cc = key[l];
                bool desc = ((tid & k) == 0);
                if (desc ? (a < cc) : (a > cc)) { key[tid] = cc; key[l] = a; }
            }
            __syncthreads();
        }
    }

    if (tid < MN) {
        ull kk = key[tid];
        int idx = (SS - 1) - (int)(kk & 0xFFFull);
        unsigned u = (unsigned)(kk >> 12);
        u = (u & 0x80000000u) ? (u & 0x7FFFFFFFu) : ~u;
        int nn = r16_nn[b];
        o_idx[b * MN + tid]  = (float)idx;
        o_ns[b * MN + tid]   = __uint_as_float(u);
        o_mask[b * MN + tid] = (tid < nn) ? 1.0f : 0.0f;
        r16_idx[b * MN + tid] = idx;
    }
}

// ---------------------------------------------------------------------------
// Kernel 5: gather enc rows.
// ---------------------------------------------------------------------------
__global__ __launch_bounds__(512) void r16_gather(
    const float* __restrict__ hidden, float* __restrict__ enc)
{
    int t = blockIdx.x;
    int b = t / MN;
    int s = r16_idx[t];
    const float4* src = (const float4*)(hidden + ((size_t)b * SS + s) * DD);
    float4* dst = (float4*)(enc + (size_t)t * DD);
    dst[threadIdx.x] = src[threadIdx.x];
}

// ---------------------------------------------------------------------------
extern "C" void kernel_launch(void* const* d_in, const int* in_sizes, int n_in,
                              void* d_out, int out_size)
{
    const float* lhs  = (const float*)d_in[0];
    const float* hid  = (const float*)d_in[1];
    const int*   mask = (const int*)  d_in[2];
    const float* w1   = (const float*)d_in[3];
    const float* b1   = (const float*)d_in[4];
    const float* w2   = (const float*)d_in[5];
    const float* b2   = (const float*)d_in[6];

    float* out = (float*)d_out;
    float* o_enc    = out;
    float* o_mask   = out + ENC_SZ;
    float* o_ns     = o_mask + BMN;
    float* o_idx    = o_ns + BMN;
    float* o_scores = o_idx + BMN;

    cudaFuncSetAttribute(r16_score,
                         cudaFuncAttributeMaxDynamicSharedMemorySize, SMEM_BYTES);

    r16_bprep<<<(HH * DD) / 256, 256>>>(w1);
    r16_score<<<MM / 128, 256, SMEM_BYTES>>>(lhs, b1, w2, b2, o_scores);
    r16_cand_topk<<<BB, 1024>>>(mask);
    r16_rescore<<<BB * NCAND / RCPB, 512>>>(lhs, w1, b1, w2, b2);
    r16_final<<<BB, NCAND>>>(o_mask, o_ns, o_idx);
    r16_gather<<<BB * MN, 512>>>(hid, o_enc);
}

// round 17
// speedup vs baseline: 1.0746x; 1.0078x over previous
#include <cuda_runtime.h>
#include <cstdint>

// ====== NuggetScorer — R16 (= R15 resubmit): TF32 rank + 4cand/warp rescore =
#define BB 8
#define SS 4096
#define DD 2048
#define HH 128
#define MN 410
#define MM (BB*SS)

#define ENC_SZ ((size_t)BB*MN*DD)
#define BMN (BB*MN)

#define NCAND 512
#define RCPB 64                // candidates per rescore block
#define RCPW 4                 // candidates per warp
#define RKC 128                // rescore k-chunk (stage 64 x 128 floats = 32KB)

// GEMM config (single-level TF32)
#define KC 16
#define NCH (DD/KC)            // 128
#define LVLF 2048
#define AFRAG LVLF             // 2048
#define BFRAG LVLF             // 2048
#define STAGEF (AFRAG+BFRAG)   // 4096
#define REDF (128*17)
#define SMEM_FLOATS (2*STAGEF + REDF + 256)
#define SMEM_BYTES (SMEM_FLOATS*4)

__device__ float r16_bfrag[NCH*BFRAG];
__device__ float r16_scores[MM];
__device__ int   r16_cand[BB*NCAND];
__device__ float r16_cscore[BB*NCAND];
__device__ int   r16_nn[BB];
__device__ int   r16_idx[BB*MN];

typedef unsigned long long ull;

__device__ __forceinline__ float r16_tf32(float x) {
    uint32_t r; asm("cvt.rna.tf32.f32 %0,%1;" : "=r"(r) : "f"(x));
    return __uint_as_float(r);
}
__device__ __forceinline__ void r16_mma(float* d, const uint32_t* a, const uint32_t* b) {
    asm volatile("mma.sync.aligned.m16n8k8.row.col.f32.tf32.tf32.f32 "
        "{%0,%1,%2,%3},{%4,%5,%6,%7},{%8,%9},{%0,%1,%2,%3};"
        : "+f"(d[0]), "+f"(d[1]), "+f"(d[2]), "+f"(d[3])
        : "r"(a[0]), "r"(a[1]), "r"(a[2]), "r"(a[3]), "r"(b[0]), "r"(b[1]));
}
__device__ __forceinline__ ull r16_pack2(float x, float y) {
    ull r; asm("mov.b64 %0,{%1,%2};" : "=l"(r) : "f"(x), "f"(y)); return r;
}
__device__ __forceinline__ void r16_unpack2(ull v, float& x, float& y) {
    asm("mov.b64 {%0,%1},%2;" : "=f"(x), "=f"(y) : "l"(v));
}
__device__ __forceinline__ void r16_ffma2(ull& d, ull a, ull b) {
    asm("fma.rn.f32x2 %0,%1,%2,%0;" : "+l"(d) : "l"(a), "l"(b));
}

// ---------------------------------------------------------------------------
// Kernel 0: W1 -> single-level tf32 fragments (fragment-major per chunk)
// ---------------------------------------------------------------------------
__global__ __launch_bounds__(256) void r16_bprep(const float* __restrict__ w1)
{
    int idx = blockIdx.x * 256 + threadIdx.x;    // 0 .. 262143
    int k = idx >> 7, n = idx & 127;
    float h0 = r16_tf32(w1[idx]);                 // w1[k][n]
    int ch = k >> 4, kk = k & 15;
    int ks = kk >> 3, c2 = kk & 7;
    int nb = n >> 3;
    int lane = ((n & 7) << 2) | (c2 & 3);
    int slot = c2 >> 2;
    r16_bfrag[ch * BFRAG + ((nb * 2 + ks) << 6) + (lane << 1) + slot] = h0;
}

// ---------------------------------------------------------------------------
// Kernel 1: approx score GEMM, single-term TF32 (mma.sync).
// ---------------------------------------------------------------------------
extern __shared__ float r16_dsm[];

__global__ __launch_bounds__(256) void r16_score(
    const float* __restrict__ A, const float* __restrict__ bias1,
    const float* __restrict__ w2v, const float* __restrict__ bias2,
    float* __restrict__ scores_out)
{
    const int tid  = threadIdx.x;
    const int lane = tid & 31;
    const int wid  = tid >> 5;
    const int wy   = wid >> 2;
    const int wx   = wid & 3;
    const int row0 = blockIdx.x * 128;

    float* red = r16_dsm + 2 * STAGEF;
    float* b1s = red + REDF;
    float* w2s = b1s + HH;
    if (tid < HH) { b1s[tid] = bias1[tid]; w2s[tid] = w2v[tid]; }

    const int rr0 = tid >> 2;
    const int q   = tid & 3;
    int aoff[8];
#pragma unroll
    for (int e = 0; e < 8; e++) {
        int rr = (e < 4) ? rr0 : rr0 + 64;
        int col = q * 4 + (e & 3);
        int ks = col >> 3, cc = col & 7;
        int mt = rr >> 4, r = rr & 15;
        int lw = ((r & 7) << 2) | (cc & 3);
        int slot = ((cc >> 2) << 1) | (r >> 3);
        aoff[e] = ((mt * 2 + ks) << 7) + (lw << 2) + slot;
    }

    float acc[4][4][4];
#pragma unroll
    for (int i = 0; i < 4; i++)
#pragma unroll
        for (int j = 0; j < 4; j++)
#pragma unroll
            for (int v = 0; v < 4; v++) acc[i][j][v] = 0.f;

    float4 sa0, sa1, sb[2];

    sa0 = *(const float4*)(A + (size_t)(row0 + rr0) * DD + q * 4);
    sa1 = *(const float4*)(A + (size_t)(row0 + rr0 + 64) * DD + q * 4);
#pragma unroll
    for (int i = 0; i < 2; i++)
        sb[i] = __ldg((const float4*)(r16_bfrag + (size_t)(tid + i * 256) * 4));

    {
        float* st = r16_dsm;
        float av[8] = {sa0.x, sa0.y, sa0.z, sa0.w, sa1.x, sa1.y, sa1.z, sa1.w};
#pragma unroll
        for (int e = 0; e < 8; e++) st[aoff[e]] = r16_tf32(av[e]);
#pragma unroll
        for (int i = 0; i < 2; i++)
            *(float4*)(st + AFRAG + (tid + i * 256) * 4) = sb[i];
    }
    __syncthreads();

    for (int c = 0; c < NCH; ++c) {
        const int cur = c & 1;
        const float* st = r16_dsm + cur * STAGEF;

        if (c + 1 < NCH) {
            int k0 = (c + 1) * KC;
            sa0 = *(const float4*)(A + (size_t)(row0 + rr0) * DD + k0 + q * 4);
            sa1 = *(const float4*)(A + (size_t)(row0 + rr0 + 64) * DD + k0 + q * 4);
#pragma unroll
            for (int i = 0; i < 2; i++)
                sb[i] = __ldg((const float4*)(r16_bfrag + (size_t)(c + 1) * BFRAG + (size_t)(tid + i * 256) * 4));
        }

#pragma unroll
        for (int ks = 0; ks < 2; ks++) {
            const float* Ab = st;
            const float* Bb = st + AFRAG;
            uint32_t a0[4][4], b0[4][2];
#pragma unroll
            for (int mt = 0; mt < 4; mt++) {
                float4 v = *(const float4*)(Ab + (((wy * 4 + mt) * 2 + ks) << 7) + (lane << 2));
                a0[mt][0] = __float_as_uint(v.x); a0[mt][1] = __float_as_uint(v.y);
                a0[mt][2] = __float_as_uint(v.z); a0[mt][3] = __float_as_uint(v.w);
            }
#pragma unroll
            for (int nt = 0; nt < 4; nt++) {
                float2 v = *(const float2*)(Bb + (((wx * 4 + nt) * 2 + ks) << 6) + (lane << 1));
                b0[nt][0] = __float_as_uint(v.x); b0[nt][1] = __float_as_uint(v.y);
            }
#pragma unroll
            for (int mt = 0; mt < 4; mt++)
#pragma unroll
                for (int nt = 0; nt < 4; nt++)
                    r16_mma(acc[mt][nt], a0[mt], b0[nt]);
        }

        if (c + 1 < NCH) {
            float* st2 = r16_dsm + (cur ^ 1) * STAGEF;
            float av[8] = {sa0.x, sa0.y, sa0.z, sa0.w, sa1.x, sa1.y, sa1.z, sa1.w};
#pragma unroll
            for (int e = 0; e < 8; e++) st2[aoff[e]] = r16_tf32(av[e]);
#pragma unroll
            for (int i = 0; i < 2; i++)
                *(float4*)(st2 + AFRAG + (tid + i * 256) * 4) = sb[i];
        }
        __syncthreads();
    }

    const int mrow = lane >> 2;
    const int kcol = lane & 3;
#pragma unroll
    for (int mt = 0; mt < 4; mt++)
#pragma unroll
        for (int h = 0; h < 2; h++) {
            int row = (wy * 4 + mt) * 16 + mrow + 8 * h;
            float part = 0.f;
#pragma unroll
            for (int nt = 0; nt < 4; nt++) {
                int col = (wx * 4 + nt) * 8 + 2 * kcol;
                float x0 = acc[mt][nt][2 * h]     + b1s[col];
                float x1 = acc[mt][nt][2 * h + 1] + b1s[col + 1];
                float g0 = 0.5f * x0 * (1.0f + erff(x0 * 0.7071067811865476f));
                float g1 = 0.5f * x1 * (1.0f + erff(x1 * 0.7071067811865476f));
                part = fmaf(g0, w2s[col], part);
                part = fmaf(g1, w2s[col + 1], part);
            }
            red[row * 17 + wx * 4 + kcol] = part;
        }
    __syncthreads();

    if (tid < 128) {
        float s = bias2[0];
#pragma unroll
        for (int j = 0; j < 16; j++) s += red[tid * 17 + j];
        scores_out[row0 + tid] = s;
        r16_scores[row0 + tid] = s;
    }
}

// ---------------------------------------------------------------------------
// Kernel 2: per-batch bitonic sort of approx scores -> top-NCAND candidates.
// ---------------------------------------------------------------------------
__global__ __launch_bounds__(1024) void r16_cand_topk(const int* __restrict__ mask)
{
    __shared__ ull key[SS];
    __shared__ int sh_cnt;
    const int b = blockIdx.x;
    const int tid = threadIdx.x;
    if (tid == 0) sh_cnt = 0;
    __syncthreads();

    const float* srow = r16_scores + (size_t)b * SS;
    const int*   mrow = mask + (size_t)b * SS;

    int cnt = 0;
    for (int i = tid; i < SS; i += 1024) {
        float f = srow[i];
        unsigned u = __float_as_uint(f);
        u = (u & 0x80000000u) ? ~u : (u | 0x80000000u);
        key[i] = ((ull)u << 12) | (ull)(SS - 1 - i);
        cnt += mrow[i];
    }
#pragma unroll
    for (int o = 16; o > 0; o >>= 1) cnt += __shfl_down_sync(0xffffffffu, cnt, o);
    if ((tid & 31) == 0) atomicAdd(&sh_cnt, cnt);
    __syncthreads();

    for (int k = 2; k <= SS; k <<= 1) {
        for (int j = k >> 1; j > 0; j >>= 1) {
            for (int i = tid; i < SS; i += 1024) {
                int l = i ^ j;
                if (l > i) {
                    ull a = key[i], cc = key[l];
                    bool desc = ((i & k) == 0);
                    if (desc ? (a < cc) : (a > cc)) { key[i] = cc; key[l] = a; }
                }
            }
            __syncthreads();
        }
    }

    if (tid == 0) {
        int ntok = sh_cnt;
        int nn = (int)ceilf((float)ntok * 0.1f);
        nn = max(nn, 1);
        nn = min(nn, ntok);
        r16_nn[b] = nn;
    }
    if (tid < NCAND)
        r16_cand[b * NCAND + tid] = (SS - 1) - (int)(key[tid] & 0xFFFull);
}

// ---------------------------------------------------------------------------
// Kernel 3: exact fp32 rescore — 4 candidates per warp (w-load amortized 4x).
// 512 threads = 16 warps; block covers 64 candidates. Lane owns 4 hidden cols.
// Per k: 1 LDG.128 (w row, warp-shared) + 4 broadcast LDS.32 (a) + 8 FFMA2.
// Serial ascending-k chain per (cand, col) — same class as R10/R12 (passed).
// ---------------------------------------------------------------------------
__global__ __launch_bounds__(512) void r16_rescore(
    const float* __restrict__ lhs, const float* __restrict__ w1,
    const float* __restrict__ bias1, const float* __restrict__ w2v,
    const float* __restrict__ bias2)
{
    __shared__ float sA[RCPB][RKC];      // 64 x 128 x 4B = 32 KB
    __shared__ int rows[RCPB];

    const int tid  = threadIdx.x;
    const int wid  = tid >> 5;           // warp -> candidates wid*4 .. +3
    const int lane = tid & 31;
    const int cand0 = blockIdx.x * RCPB;
    const int b = cand0 / NCAND;

    if (tid < RCPB) rows[tid] = r16_cand[cand0 + tid];
    __syncthreads();

    ull h2[RCPW][2];
#pragma unroll
    for (int c = 0; c < RCPW; c++) { h2[c][0] = 0ull; h2[c][1] = 0ull; }

    const float* wcol = w1 + lane * 4;

    for (int ch = 0; ch < DD / RKC; ch++) {     // 16 chunks
        // stage 64 candidate rows x RKC floats (coalesced, 4 float4/thread)
#pragma unroll
        for (int s = 0; s < 4; s++) {
            int lin = tid + s * 512;            // 0..2047
            int r = lin >> 5, c4 = lin & 31;
            *(float4*)(&sA[r][c4 * 4]) =
                *(const float4*)(lhs + ((size_t)b * SS + rows[r]) * DD + ch * RKC + c4 * 4);
        }
        __syncthreads();

        const float* a0 = sA[wid * RCPW + 0];
        const float* a1 = sA[wid * RCPW + 1];
        const float* a2 = sA[wid * RCPW + 2];
        const float* a3 = sA[wid * RCPW + 3];

#pragma unroll 4
        for (int k = 0; k < RKC; k++) {
            float4 w4 = __ldg((const float4*)(wcol + (size_t)(ch * RKC + k) * HH));
            ull wlo = r16_pack2(w4.x, w4.y);
            ull whi = r16_pack2(w4.z, w4.w);
            ull ap0 = r16_pack2(a0[k], a0[k]);
            ull ap1 = r16_pack2(a1[k], a1[k]);
            ull ap2 = r16_pack2(a2[k], a2[k]);
            ull ap3 = r16_pack2(a3[k], a3[k]);
            r16_ffma2(h2[0][0], wlo, ap0); r16_ffma2(h2[0][1], whi, ap0);
            r16_ffma2(h2[1][0], wlo, ap1); r16_ffma2(h2[1][1], whi, ap1);
            r16_ffma2(h2[2][0], wlo, ap2); r16_ffma2(h2[2][1], whi, ap2);
            r16_ffma2(h2[3][0], wlo, ap3); r16_ffma2(h2[3][1], whi, ap3);
        }
        __syncthreads();
    }

    // epilogue: per candidate: gelu + dot(w2) over lane's 4 cols, warp reduce
    float b1v[4], w2vv[4];
#pragma unroll
    for (int t = 0; t < 4; t++) {
        b1v[t]  = __ldg(bias1 + lane * 4 + t);
        w2vv[t] = __ldg(w2v + lane * 4 + t);
    }
    float bb2 = bias2[0];
#pragma unroll
    for (int c = 0; c < RCPW; c++) {
        float h[4];
        r16_unpack2(h2[c][0], h[0], h[1]);
        r16_unpack2(h2[c][1], h[2], h[3]);
        float p = 0.f;
#pragma unroll
        for (int t = 0; t < 4; t++) {
            float x = h[t] + b1v[t];
            float g = 0.5f * x * (1.0f + erff(x * 0.7071067811865476f));
            p = fmaf(g, w2vv[t], p);
        }
#pragma unroll
        for (int o = 16; o > 0; o >>= 1) p += __shfl_down_sync(0xffffffffu, p, o);
        if (lane == 0) r16_cscore[cand0 + wid * RCPW + c] = p + bb2;
    }
}

// ---------------------------------------------------------------------------
// Kernel 4: final per-batch sort of NCAND rescored candidates -> outputs.
// ---------------------------------------------------------------------------
__global__ __launch_bounds__(NCAND) void r16_final(
    float* __restrict__ o_mask, float* __restrict__ o_ns, float* __restrict__ o_idx)
{
    __shared__ ull key[NCAND];
    const int b = blockIdx.x;
    const int tid = threadIdx.x;

    {
        float f = r16_cscore[b * NCAND + tid];
        int idx = r16_cand[b * NCAND + tid];
        unsigned u = __float_as_uint(f);
        u = (u & 0x80000000u) ? ~u : (u | 0x80000000u);
        key[tid] = ((ull)u << 12) | (ull)(SS - 1 - idx);
    }
    __syncthreads();

    for (int k = 2; k <= NCAND; k <<= 1) {
        for (int j = k >> 1; j > 0; j >>= 1) {
            int l = tid ^ j;
            if (l > tid) {
                ull a = key[tid], cc = key[l];
                bool desc = ((tid & k) == 0);
                if (desc ? (a < cc) : (a > cc)) { key[tid] = cc; key[l] = a; }
            }
            __syncthreads();
        }
    }

    if (tid < MN) {
        ull kk = key[tid];
        int idx = (SS - 1) - (int)(kk & 0xFFFull);
        unsigned u = (unsigned)(kk >> 12);
        u = (u & 0x80000000u) ? (u & 0x7FFFFFFFu) : ~u;
        int nn = r16_nn[b];
        o_idx[b * MN + tid]  = (float)idx;
        o_ns[b * MN + tid]   = __uint_as_float(u);
        o_mask[b * MN + tid] = (tid < nn) ? 1.0f : 0.0f;
        r16_idx[b * MN + tid] = idx;
    }
}

// ---------------------------------------------------------------------------
// Kernel 5: gather enc rows.
// ---------------------------------------------------------------------------
__global__ __launch_bounds__(512) void r16_gather(
    const float* __restrict__ hidden, float* __restrict__ enc)
{
    int t = blockIdx.x;
    int b = t / MN;
    int s = r16_idx[t];
    const float4* src = (const float4*)(hidden + ((size_t)b * SS + s) * DD);
    float4* dst = (float4*)(enc + (size_t)t * DD);
    dst[threadIdx.x] = src[threadIdx.x];
}

// ---------------------------------------------------------------------------
extern "C" void kernel_launch(void* const* d_in, const int* in_sizes, int n_in,
                              void* d_out, int out_size)
{
    const float* lhs  = (const float*)d_in[0];
    const float* hid  = (const float*)d_in[1];
    const int*   mask = (const int*)  d_in[2];
    const float* w1   = (const float*)d_in[3];
    const float* b1   = (const float*)d_in[4];
    const float* w2   = (const float*)d_in[5];
    const float* b2   = (const float*)d_in[6];

    float* out = (float*)d_out;
    float* o_enc    = out;
    float* o_mask   = out + ENC_SZ;
    float* o_ns     = o_mask + BMN;
    float* o_idx    = o_ns + BMN;
    float* o_scores = o_idx + BMN;

    cudaFuncSetAttribute(r16_score,
                         cudaFuncAttributeMaxDynamicSharedMemorySize, SMEM_BYTES);

    r16_bprep<<<(HH * DD) / 256, 256>>>(w1);
    r16_score<<<MM / 128, 256, SMEM_BYTES>>>(lhs, b1, w2, b2, o_scores);
    r16_cand_topk<<<BB, 1024>>>(mask);
    r16_rescore<<<BB * NCAND / RCPB, 512>>>(lhs, w1, b1, w2, b2);
    r16_final<<<BB, NCAND>>>(o_mask, o_ns, o_idx);
    r16_gather<<<BB * MN, 512>>>(hid, o_enc);
}